// round 9
// baseline (speedup 1.0000x reference)
#include <cuda_runtime.h>
#include <stdint.h>

#define NB_COUNT 32
#define DIM 128           // floats per row
#define VEC2 (DIM / 2)    // 64 float2 per row

// One warp per TWO nodes, LDG.64 gathers (R8's sweet spot geometry).
// The two nodes' load streams are fully independent, so each loop iteration
// issues 4 independent LDG.64s — double the per-warp MLP vs R8 without
// relying on ptxas front-batching (which R2 showed it refuses to do across
// accumulator-carried iterations).
__global__ __launch_bounds__(256) void sum_agg_kernel(
    const int* __restrict__ neighs,
    const float2* __restrict__ emb,   // [num_ids][64] float2
    float2* __restrict__ out,         // [node_count][64] float2
    int node_count)
{
    const int warp  = (blockIdx.x * blockDim.x + threadIdx.x) >> 5;
    const int lane  = threadIdx.x & 31;
    const int nodeA = warp * 2;
    const int nodeB = nodeA + 1;
    if (nodeA >= node_count) return;
    const bool hasB = (nodeB < node_count);

    // Coalesced index loads: lane l gets neighbor l of each node.
    const int idxA = neighs[(size_t)nodeA * NB_COUNT + lane];
    const int idxB = hasB ? neighs[(size_t)nodeB * NB_COUNT + lane] : idxA;

    float aA0x = 0.f, aA0y = 0.f, aA1x = 0.f, aA1y = 0.f;
    float aB0x = 0.f, aB0y = 0.f, aB1x = 0.f, aB1y = 0.f;

    #pragma unroll
    for (int j = 0; j < NB_COUNT; ++j) {
        const int rA = __shfl_sync(0xffffffffu, idxA, j);
        const int rB = __shfl_sync(0xffffffffu, idxB, j);
        const float2* rowA = emb + (size_t)rA * VEC2 + lane;
        const float2* rowB = emb + (size_t)rB * VEC2 + lane;
        // 4 independent LDG.64s (2 lines each) — no cross-deps.
        const float2 vA0 = __ldg(rowA);
        const float2 vA1 = __ldg(rowA + 32);
        const float2 vB0 = __ldg(rowB);
        const float2 vB1 = __ldg(rowB + 32);
        aA0x += vA0.x; aA0y += vA0.y;
        aA1x += vA1.x; aA1y += vA1.y;
        aB0x += vB0.x; aB0y += vB0.y;
        aB1x += vB1.x; aB1y += vB1.y;
    }

    float2* oA = out + (size_t)nodeA * VEC2 + lane;
    oA[0]  = make_float2(aA0x, aA0y);
    oA[32] = make_float2(aA1x, aA1y);
    if (hasB) {
        float2* oB = out + (size_t)nodeB * VEC2 + lane;
        oB[0]  = make_float2(aB0x, aB0y);
        oB[32] = make_float2(aB1x, aB1y);
    }
}

extern "C" void kernel_launch(void* const* d_in, const int* in_sizes, int n_in,
                              void* d_out, int out_size)
{
    // metadata order: neighs (int32), node_count (int scalar), emb_table (f32)
    const int* neighs = (const int*)d_in[0];
    const float2* emb = (const float2*)d_in[2];
    float2* out = (float2*)d_out;

    const int node_count = out_size / DIM;   // out is [node_count, 128] f32

    const int threads = 256;                  // 8 warps = 16 nodes per block
    const int warps_needed = (node_count + 1) / 2;
    const int blocks = (warps_needed * 32 + threads - 1) / threads;

    sum_agg_kernel<<<blocks, threads>>>(neighs, emb, out, node_count);
}

// round 10
// speedup vs baseline: 1.0625x; 1.0625x over previous
#include <cuda_runtime.h>
#include <stdint.h>

#define NB_COUNT 32
#define DIM 128           // floats per row
#define VEC2 (DIM / 2)    // 64 float2 per row

// One warp per TWO nodes, LDG.64 gathers, with an explicit register budget.
// R9 failed because the default ptxas budget (32 regs) forced serialization
// of the second node's load stream. __launch_bounds__(256, 4) allows 64 regs
// so all 4 independent LDG.64s per iteration stay in flight (2x MLP vs R8).
__global__ __launch_bounds__(256, 4) void sum_agg_kernel(
    const int* __restrict__ neighs,
    const float2* __restrict__ emb,   // [num_ids][64] float2
    float2* __restrict__ out,         // [node_count][64] float2
    int node_count)
{
    const int warp  = (blockIdx.x * blockDim.x + threadIdx.x) >> 5;
    const int lane  = threadIdx.x & 31;
    const int nodeA = warp * 2;
    const int nodeB = nodeA + 1;
    if (nodeA >= node_count) return;
    const bool hasB = (nodeB < node_count);

    // Coalesced index loads: lane l gets neighbor l of each node.
    const int idxA = neighs[(size_t)nodeA * NB_COUNT + lane];
    const int idxB = hasB ? neighs[(size_t)nodeB * NB_COUNT + lane] : idxA;

    float aA0x = 0.f, aA0y = 0.f, aA1x = 0.f, aA1y = 0.f;
    float aB0x = 0.f, aB0y = 0.f, aB1x = 0.f, aB1y = 0.f;

    // Unroll by 2 neighbors -> 8 independent LDG.64s visible per iteration.
    #pragma unroll
    for (int j = 0; j < NB_COUNT; j += 2) {
        const int rA0 = __shfl_sync(0xffffffffu, idxA, j);
        const int rA1 = __shfl_sync(0xffffffffu, idxA, j + 1);
        const int rB0 = __shfl_sync(0xffffffffu, idxB, j);
        const int rB1 = __shfl_sync(0xffffffffu, idxB, j + 1);
        const float2* pA0 = emb + (size_t)rA0 * VEC2 + lane;
        const float2* pA1 = emb + (size_t)rA1 * VEC2 + lane;
        const float2* pB0 = emb + (size_t)rB0 * VEC2 + lane;
        const float2* pB1 = emb + (size_t)rB1 * VEC2 + lane;

        const float2 vA0a = __ldg(pA0);
        const float2 vA0b = __ldg(pA0 + 32);
        const float2 vA1a = __ldg(pA1);
        const float2 vA1b = __ldg(pA1 + 32);
        const float2 vB0a = __ldg(pB0);
        const float2 vB0b = __ldg(pB0 + 32);
        const float2 vB1a = __ldg(pB1);
        const float2 vB1b = __ldg(pB1 + 32);

        aA0x += vA0a.x; aA0y += vA0a.y;
        aA1x += vA0b.x; aA1y += vA0b.y;
        aA0x += vA1a.x; aA0y += vA1a.y;
        aA1x += vA1b.x; aA1y += vA1b.y;
        aB0x += vB0a.x; aB0y += vB0a.y;
        aB1x += vB0b.x; aB1y += vB0b.y;
        aB0x += vB1a.x; aB0y += vB1a.y;
        aB1x += vB1b.x; aB1y += vB1b.y;
    }

    float2* oA = out + (size_t)nodeA * VEC2 + lane;
    oA[0]  = make_float2(aA0x, aA0y);
    oA[32] = make_float2(aA1x, aA1y);
    if (hasB) {
        float2* oB = out + (size_t)nodeB * VEC2 + lane;
        oB[0]  = make_float2(aB0x, aB0y);
        oB[32] = make_float2(aB1x, aB1y);
    }
}

extern "C" void kernel_launch(void* const* d_in, const int* in_sizes, int n_in,
                              void* d_out, int out_size)
{
    // metadata order: neighs (int32), node_count (int scalar), emb_table (f32)
    const int* neighs = (const int*)d_in[0];
    const float2* emb = (const float2*)d_in[2];
    float2* out = (float2*)d_out;

    const int node_count = out_size / DIM;   // out is [node_count, 128] f32

    const int threads = 256;                  // 8 warps = 16 nodes per block
    const int warps_needed = (node_count + 1) / 2;
    const int blocks = (warps_needed * 32 + threads - 1) / threads;

    sum_agg_kernel<<<blocks, threads>>>(neighs, emb, out, node_count);
}